// round 11
// baseline (speedup 1.0000x reference)
#include <cuda_runtime.h>
#include <cuda_bf16.h>
#include <cstdint>

// AFM forward, algebraically collapsed (softmax over size-1 axis == 1):
//   x[b]   = 0.5*(||sum_f emb_f||^2 - sum_f ||emb_f||^2)
//   out[b] = sigmoid(x[b]*out_kernel + out_bias)
//
// Shape: ONE WARP PER ROW, 1024 CTAs x 128 threads (best measured, R10).
// Change vs R10: gather loads carry the PTX L2::64B prefetch-size
// qualifier. Measured DRAM traffic is exactly 2x the requested bytes
// (128B line fetch per random 64B embedding). If the per-instruction
// hint overrides the default 128B fetch granularity, DRAM bytes halve.

#define B_ROWS   4096
#define N_SPARSE 26
#define VOCAB    100000

__device__ __forceinline__ float4 ldg_64b_v4(const float4* p) {
    float4 v;
    asm("ld.global.nc.L2::64B.v4.f32 {%0,%1,%2,%3}, [%4];"
        : "=f"(v.x), "=f"(v.y), "=f"(v.z), "=f"(v.w)
        : "l"(p));
    return v;
}

__global__ void __launch_bounds__(128) afm_gather_kernel(
    const int*    __restrict__ ids,     // [B, 26]
    const float4* __restrict__ table,   // [26, VOCAB, 4] float4 units
    const float*  __restrict__ out_k,   // [1]
    const float*  __restrict__ out_b,   // [1]
    float*        __restrict__ out)     // [B]
{
    const unsigned FULL = 0xffffffffu;
    const int gtid = blockIdx.x * blockDim.x + threadIdx.x;
    const int row  = gtid >> 5;            // one warp per row (grid exact)
    const int lane = threadIdx.x & 31;

    const int slice = lane & 3;            // float4 slice of the embedding
    const int fg    = lane >> 2;           // field-in-group 0..7

    const int* rid = ids + row * N_SPARSE;

    const float okv = __ldg(out_k);
    const float obv = __ldg(out_b);

    // Front-batched id loads: unconditional, clamped in-row (4-lane bcast).
    int idr[4];
    #pragma unroll
    for (int r = 0; r < 4; ++r) {
        int f = r * 8 + fg;
        idr[r] = __ldg(rid + (f < N_SPARSE ? f : N_SPARSE - 1));
    }

    float4 S = make_float4(0.f, 0.f, 0.f, 0.f);
    float  q = 0.f;

    // 4 independent 16B gathers per lane; 4 adjacent lanes coalesce into
    // one 64B request per embedding (minimal request count). L2::64B hint
    // asks the LTS to fetch only the needed 64B half-line from DRAM.
    #pragma unroll
    for (int r = 0; r < 4; ++r) {
        const int f = r * 8 + fg;
        if (f < N_SPARSE) {
            const float4 v = ldg_64b_v4(table + (size_t)f * (VOCAB * 4)
                                              + (size_t)idr[r] * 4 + slice);
            S.x += v.x; S.y += v.y; S.z += v.z; S.w += v.w;
            q   += v.x * v.x + v.y * v.y + v.z * v.z + v.w * v.w;
        }
    }

    // Reduce S and q over the field dimension (lane bits 2,3,4).
    #pragma unroll
    for (int d = 4; d <= 16; d <<= 1) {
        S.x += __shfl_xor_sync(FULL, S.x, d);
        S.y += __shfl_xor_sync(FULL, S.y, d);
        S.z += __shfl_xor_sync(FULL, S.z, d);
        S.w += __shfl_xor_sync(FULL, S.w, d);
        q   += __shfl_xor_sync(FULL, q, d);
    }

    // Lanes 0..3 hold per-slice totals; merged tail reduction.
    float t = S.x * S.x + S.y * S.y + S.z * S.z + S.w * S.w - q;
    t += __shfl_xor_sync(FULL, t, 1);
    t += __shfl_xor_sync(FULL, t, 2);

    if (lane == 0) {
        const float z = 0.5f * t * okv + obv;   // t == 2*sum_{i<j} e_i.e_j
        out[row] = 1.0f / (1.0f + __expf(-z));
    }
}

extern "C" void kernel_launch(void* const* d_in, const int* in_sizes, int n_in,
                              void* d_out, int out_size)
{
    (void)in_sizes; (void)n_in; (void)out_size;
    const int*    ids   = (const int*)   d_in[1];
    const float4* table = (const float4*)d_in[2];
    const float*  out_k = (const float*) d_in[7];
    const float*  out_b = (const float*) d_in[8];
    float*        out   = (float*)       d_out;

    const int threads = 128;                     // 4 warps = 4 rows / block
    const int blocks  = (B_ROWS * 32) / threads; // 1024 blocks, exact
    afm_gather_kernel<<<blocks, threads>>>(ids, table, out_k, out_b, out);
}